// round 3
// baseline (speedup 1.0000x reference)
#include <cuda_runtime.h>
#include <float.h>

// Problem shape (RLFrameSelector): x[B,T,F], W1[F,U], b1[U], W2[U,1], b2[1], k
#define BB 32
#define TT 2048
#define FF 512
#define UU 128
#define BT (BB * TT)      // 65536 frames
#define KC 32             // features per chunk
#define NCHUNK (FF / KC)  // 16
#define FRB 32            // frames per block
#define WSROW 36          // padded ws row length in words (conflict-free LDS.128)
#define NEG_BIG (-1.0e9f)

// Scratch (device globals: no allocation allowed)
__device__ float g_scores[BT];
__device__ int   g_sel[BT];
__device__ float g_W1T[UU * FF];   // W1 transposed: [u][f]

// ---------------- packed f32x2 helpers (Blackwell FFMA2) ----------------
__device__ __forceinline__ unsigned long long fma2(unsigned long long a,
                                                   unsigned long long b,
                                                   unsigned long long c) {
    unsigned long long d;
    asm("fma.rn.f32x2 %0, %1, %2, %3;" : "=l"(d) : "l"(a), "l"(b), "l"(c));
    return d;
}
__device__ __forceinline__ float2 unpack2(unsigned long long v) {
    float2 r;
    asm("mov.b64 {%0, %1}, %2;" : "=f"(r.x), "=f"(r.y) : "l"(v));
    return r;
}
__device__ __forceinline__ void cpasync16(void* dst, const void* src) {
    unsigned d = (unsigned)__cvta_generic_to_shared(dst);
    asm volatile("cp.async.cg.shared.global [%0], [%1], 16;" :: "r"(d), "l"(src));
}

// ---------------- Kernel 0: transpose W1[f][u] -> W1T[u][f] ------------------
__global__ void transpose_W1(const float* __restrict__ W1) {
    __shared__ float tile[32][33];
    const int bx = blockIdx.x;   // f tile (0..15)
    const int by = blockIdx.y;   // u tile (0..3)
    const int tx = threadIdx.x;  // 0..31
    const int ty = threadIdx.y;  // 0..7
#pragma unroll
    for (int i = 0; i < 32; i += 8) {
        const int f = bx * 32 + ty + i;
        const int u = by * 32 + tx;
        tile[ty + i][tx] = W1[f * UU + u];
    }
    __syncthreads();
#pragma unroll
    for (int i = 0; i < 32; i += 8) {
        const int u = by * 32 + ty + i;
        const int f = bx * 32 + tx;
        g_W1T[u * FF + f] = tile[tx][ty + i];
    }
}

// ---------------- Kernel 1: scores = relu(x@W1 + b1) @ W2 (masked) ----------
// 256 threads / 8 warps. Warp owns 4 frames x all 128 u; lane l owns
// u in {l, l+32, l+64, l+96}. f32x2 lanes pair ADJACENT K indices:
// both x pairs (frame-major rows) and W pairs (W1T rows) are natural ->
// zero dup-MOVs, contiguous cp.async staging, ping-pong double buffer.
__global__ __launch_bounds__(256, 3)
void scores_kernel(const float* __restrict__ x,
                   const float* __restrict__ b1,
                   const float* __restrict__ W2) {
    __shared__ float xs[2][FRB * KC];     // [buf][fr*KC + f]   4KB each
    __shared__ float ws[2][UU * WSROW];   // [buf][u*36 + f]   18KB each
    __shared__ int   nzs[FRB];

    const int t = threadIdx.x;
    const int w = t >> 5;
    const int l = t & 31;
    const int fb = blockIdx.x * FRB;

    if (t < FRB) nzs[t] = 0;
    __syncthreads();   // zero-init must precede any nz set (race otherwise)

    // staging mapping: thread t stages 16B group sj of frame sfr (x),
    // and 4x 16B groups of W1T rows (cp.async).
    const int sfr = t >> 3;          // 0..31
    const int sj  = (t & 7) * 4;     // word offset in chunk row
    const float* xsrc = x + (size_t)(fb + sfr) * FF + sj;

    // ---- prologue: stage chunk 0 ----
    {
#pragma unroll
        for (int k2 = 0; k2 < 4; ++k2) {
            const int idx = t + 256 * k2;
            const int u = idx >> 3, jj = (idx & 7) * 4;
            cpasync16(&ws[0][u * WSROW + jj], &g_W1T[u * FF + jj]);
        }
        asm volatile("cp.async.commit_group;");
        const float4 v = *(const float4*)xsrc;
        if (v.x != 0.f || v.y != 0.f || v.z != 0.f || v.w != 0.f) nzs[sfr] = 1;
        *(float4*)&xs[0][sfr * KC + sj] = v;
        asm volatile("cp.async.wait_group 0;" ::: "memory");
    }
    __syncthreads();

    unsigned long long acc[4][4];
#pragma unroll
    for (int i = 0; i < 4; ++i)
#pragma unroll
        for (int j = 0; j < 4; ++j) acc[i][j] = 0ull;

    const int xoff = (w * 4) * KC;   // warp's first frame row (words)
    const int woff = l * WSROW;      // lane's first u row (words)

    for (int c = 0; c < NCHUNK; ++c) {
        const int cur = c & 1, nxt = cur ^ 1;
        const bool pf = (c + 1 < NCHUNK);
        float4 v;
        if (pf) {
            // prefetch chunk c+1: W via cp.async, x via LDG (checked for nz)
#pragma unroll
            for (int k2 = 0; k2 < 4; ++k2) {
                const int idx = t + 256 * k2;
                const int u = idx >> 3, jj = (idx & 7) * 4;
                cpasync16(&ws[nxt][u * WSROW + jj],
                          &g_W1T[u * FF + (c + 1) * KC + jj]);
            }
            asm volatile("cp.async.commit_group;");
            v = *(const float4*)(xsrc + (c + 1) * KC);
        }
        // ---- compute chunk cur: 8 fully-unrolled 4-f steps ----
        const float* xb = &xs[cur][xoff];
        const float* wb = &ws[cur][woff];
#pragma unroll
        for (int s = 0; s < KC / 4; ++s) {
            ulonglong2 xp[4];
#pragma unroll
            for (int i = 0; i < 4; ++i)
                xp[i] = *(const ulonglong2*)&xb[i * KC + 4 * s];  // broadcast
#pragma unroll
            for (int j = 0; j < 4; ++j) {
                const ulonglong2 wp =
                    *(const ulonglong2*)&wb[j * 32 * WSROW + 4 * s];
#pragma unroll
                for (int i = 0; i < 4; ++i) {
                    acc[i][j] = fma2(xp[i].x, wp.x, acc[i][j]);
                    acc[i][j] = fma2(xp[i].y, wp.y, acc[i][j]);
                }
            }
        }
        if (pf) {
            if (v.x != 0.f || v.y != 0.f || v.z != 0.f || v.w != 0.f) nzs[sfr] = 1;
            *(float4*)&xs[nxt][sfr * KC + sj] = v;
            asm volatile("cp.async.wait_group 0;" ::: "memory");
        }
        __syncthreads();
    }

    // ---- epilogue: relu(+b1)*W2, lane-reduce over u, write scores ----
    // b2 omitted: rank-invariant shift.
    float b1v[4], w2v[4];
#pragma unroll
    for (int j = 0; j < 4; ++j) {
        b1v[j] = b1[l + 32 * j];
        w2v[j] = W2[l + 32 * j];
    }
#pragma unroll
    for (int i = 0; i < 4; ++i) {
        float s_ = 0.f;
#pragma unroll
        for (int j = 0; j < 4; ++j) {
            const float2 p = unpack2(acc[i][j]);
            s_ += fmaxf(p.x + p.y + b1v[j], 0.f) * w2v[j];
        }
#pragma unroll
        for (int off = 16; off > 0; off >>= 1)
            s_ += __shfl_xor_sync(0xffffffffu, s_, off);
        if (l == 0) {
            const int fr = fb + w * 4 + i;
            g_scores[fr] = nzs[w * 4 + i] ? s_ : NEG_BIG;
        }
    }
}

// ---------------- Kernel 2: per-row top-k (iterative argmax, index tiebreak) -
__global__ void topk_kernel(const int* __restrict__ kp) {
    __shared__ float sv[TT];
    __shared__ float bw[8];
    __shared__ int   bi[8];
    const int b = blockIdx.x;
    const int t = threadIdx.x;
    const float* row = g_scores + b * TT;
    int* selrow = g_sel + b * TT;

    for (int i = t; i < TT; i += 256) { sv[i] = row[i]; selrow[i] = 0; }
    __syncthreads();

    int k = kp[0];
    if (k <= 0 || k > TT) k = 64;

    for (int it = 0; it < k; ++it) {
        float best = -FLT_MAX;
        int bidx = TT;
        for (int i = t; i < TT; i += 256) {
            const float v = sv[i];
            if (v > best || (v == best && i < bidx)) { best = v; bidx = i; }
        }
#pragma unroll
        for (int off = 16; off > 0; off >>= 1) {
            const float ov = __shfl_xor_sync(0xffffffffu, best, off);
            const int   oi = __shfl_xor_sync(0xffffffffu, bidx, off);
            if (ov > best || (ov == best && oi < bidx)) { best = ov; bidx = oi; }
        }
        if ((t & 31) == 0) { bw[t >> 5] = best; bi[t >> 5] = bidx; }
        __syncthreads();
        if (t == 0) {
            float b0 = bw[0]; int i0 = bi[0];
#pragma unroll
            for (int j = 1; j < 8; ++j)
                if (bw[j] > b0 || (bw[j] == b0 && bi[j] < i0)) { b0 = bw[j]; i0 = bi[j]; }
            sv[i0] = -FLT_MAX;
            selrow[i0] = 1;
        }
        __syncthreads();
    }
}

// ---------------- Kernel 3: out = sel ? x : 0 ------------------------------
__global__ __launch_bounds__(128)
void scatter_kernel(const float* __restrict__ x, float* __restrict__ out) {
    const int frame = blockIdx.x;
    const int t = threadIdx.x;
    const int s = g_sel[frame];
    const size_t base = (size_t)frame * FF + (size_t)t * 4;
    float4* o = (float4*)(out + base);
    if (s) *o = *(const float4*)(x + base);
    else   *o = make_float4(0.f, 0.f, 0.f, 0.f);
}

extern "C" void kernel_launch(void* const* d_in, const int* in_sizes, int n_in,
                              void* d_out, int out_size) {
    const float* x  = (const float*)d_in[0];
    const float* W1 = (const float*)d_in[1];
    const float* b1 = (const float*)d_in[2];
    const float* W2 = (const float*)d_in[3];
    // d_in[4] = b2: rank-invariant, unused.
    const int*   kp = (const int*)d_in[5];
    float* out = (float*)d_out;

    transpose_W1<<<dim3(16, 4), dim3(32, 8)>>>(W1);
    scores_kernel<<<BT / FRB, 256>>>(x, b1, W2);
    topk_kernel<<<BB, 256>>>(kp);
    scatter_kernel<<<BT, 128>>>(x, out);
}

// round 4
// speedup vs baseline: 1.1776x; 1.1776x over previous
#include <cuda_runtime.h>
#include <float.h>

// Problem shape (RLFrameSelector): x[B,T,F], W1[F,U], b1[U], W2[U,1], b2[1], k
#define BB 32
#define TT 2048
#define FF 512
#define UU 128
#define BT (BB * TT)      // 65536 frames
#define KC 32             // features per chunk
#define NCHUNK (FF / KC)  // 16
#define FRB 64            // frames per block (8 per warp)
#define WSROW 36          // padded ws row length in words (conflict-free LDS.128)
#define NEG_BIG (-1.0e9f)

#define XS_FLOATS (FRB * KC)        // 2048
#define WS_FLOATS (UU * WSROW)      // 4608
#define SMEM_BYTES ((2 * XS_FLOATS + 2 * WS_FLOATS) * 4 + FRB * 4)  // 53504 B

// Scratch (device globals: no allocation allowed)
__device__ float g_scores[BT];
__device__ int   g_sel[BT];
__device__ float g_W1T[UU * FF];   // W1 transposed: [u][f]

// ---------------- packed f32x2 helpers (Blackwell FFMA2) ----------------
__device__ __forceinline__ unsigned long long fma2(unsigned long long a,
                                                   unsigned long long b,
                                                   unsigned long long c) {
    unsigned long long d;
    asm("fma.rn.f32x2 %0, %1, %2, %3;" : "=l"(d) : "l"(a), "l"(b), "l"(c));
    return d;
}
__device__ __forceinline__ float2 unpack2(unsigned long long v) {
    float2 r;
    asm("mov.b64 {%0, %1}, %2;" : "=f"(r.x), "=f"(r.y) : "l"(v));
    return r;
}
__device__ __forceinline__ void cpasync16(void* dst, const void* src) {
    unsigned d = (unsigned)__cvta_generic_to_shared(dst);
    asm volatile("cp.async.cg.shared.global [%0], [%1], 16;" :: "r"(d), "l"(src));
}

// ---------------- Kernel 0: transpose W1[f][u] -> W1T[u][f] ------------------
__global__ void transpose_W1(const float* __restrict__ W1) {
    __shared__ float tile[32][33];
    const int bx = blockIdx.x;   // f tile (0..15)
    const int by = blockIdx.y;   // u tile (0..3)
    const int tx = threadIdx.x;  // 0..31
    const int ty = threadIdx.y;  // 0..7
#pragma unroll
    for (int i = 0; i < 32; i += 8) {
        const int f = bx * 32 + ty + i;
        const int u = by * 32 + tx;
        tile[ty + i][tx] = W1[f * UU + u];
    }
    __syncthreads();
#pragma unroll
    for (int i = 0; i < 32; i += 8) {
        const int u = by * 32 + ty + i;
        const int f = bx * 32 + tx;
        g_W1T[u * FF + f] = tile[tx][ty + i];
    }
}

// ---------------- Kernel 1: scores = relu(x@W1 + b1) @ W2 (masked) ----------
// 256 threads / 8 warps. Warp owns 8 frames x all 128 u; lane l owns
// u in {l, l+32, l+64, l+96}. f32x2 lanes pair ADJACENT K indices ->
// W pairs come free from W1T rows (no dup MOVs), x pairs from frame rows.
// Per 4-f step: 4 W-LDS.128 + 8 broadcast x-LDS.128 feed 64 FFMA2
// (crossbar 24 cyc < FMA 32 cyc per warp-step -> FMA-pipe bound).
__global__ __launch_bounds__(256, 2)
void scores_kernel(const float* __restrict__ x,
                   const float* __restrict__ b1,
                   const float* __restrict__ W2) {
    extern __shared__ float sm[];
    float* xs = sm;                                    // [2][FRB*KC]
    float* ws = sm + 2 * XS_FLOATS;                    // [2][UU*WSROW]
    int*   nzs = (int*)(sm + 2 * XS_FLOATS + 2 * WS_FLOATS);

    const int t = threadIdx.x;
    const int w = t >> 5;
    const int l = t & 31;
    const int fb = blockIdx.x * FRB;

    if (t < FRB) nzs[t] = 0;
    __syncthreads();   // nz zero-init before any set

    // x staging: 512 float4 per chunk / 256 thr = 2 each.
    // r=0: frame t>>3; r=1: frame (t>>3)+32; word j = (t&7)*4
    const int sfr = t >> 3;
    const int sj  = (t & 7) * 4;
    const float* xsrc0 = x + (size_t)(fb + sfr) * FF + sj;
    const float* xsrc1 = x + (size_t)(fb + sfr + 32) * FF + sj;
    const int xd0 = sfr * KC + sj;
    const int xd1 = (sfr + 32) * KC + sj;

    // ---- prologue: stage chunk 0 ----
    {
#pragma unroll
        for (int k2 = 0; k2 < 4; ++k2) {
            const int idx = t + 256 * k2;
            const int u = idx >> 3, jj = (idx & 7) * 4;
            cpasync16(&ws[u * WSROW + jj], &g_W1T[u * FF + jj]);
        }
        asm volatile("cp.async.commit_group;");
        const float4 v0 = *(const float4*)xsrc0;
        const float4 v1 = *(const float4*)xsrc1;
        if (v0.x != 0.f || v0.y != 0.f || v0.z != 0.f || v0.w != 0.f) nzs[sfr] = 1;
        if (v1.x != 0.f || v1.y != 0.f || v1.z != 0.f || v1.w != 0.f) nzs[sfr + 32] = 1;
        *(float4*)&xs[xd0] = v0;
        *(float4*)&xs[xd1] = v1;
        asm volatile("cp.async.wait_group 0;" ::: "memory");
    }
    __syncthreads();

    unsigned long long acc[8][4];
#pragma unroll
    for (int i = 0; i < 8; ++i)
#pragma unroll
        for (int j = 0; j < 4; ++j) acc[i][j] = 0ull;

    const int xoff = (w * 8) * KC;   // warp's first frame row (words)
    const int woff = l * WSROW;      // lane's first u row (words)

    for (int c = 0; c < NCHUNK; ++c) {
        const int cur = c & 1, nxt = cur ^ 1;
        const bool pf = (c + 1 < NCHUNK);
        float4 v0, v1;
        if (pf) {
            // prefetch chunk c+1: W via cp.async, x via LDG (nz-checked)
#pragma unroll
            for (int k2 = 0; k2 < 4; ++k2) {
                const int idx = t + 256 * k2;
                const int u = idx >> 3, jj = (idx & 7) * 4;
                cpasync16(&ws[nxt * WS_FLOATS + u * WSROW + jj],
                          &g_W1T[u * FF + (c + 1) * KC + jj]);
            }
            asm volatile("cp.async.commit_group;");
            v0 = *(const float4*)(xsrc0 + (c + 1) * KC);
            v1 = *(const float4*)(xsrc1 + (c + 1) * KC);
        }
        // ---- compute chunk cur: 8 fully-unrolled 4-f steps ----
        const float* xb = &xs[cur * XS_FLOATS + xoff];
        const float* wb = &ws[cur * WS_FLOATS + woff];
#pragma unroll
        for (int s = 0; s < KC / 4; ++s) {
            ulonglong2 wq[4];
#pragma unroll
            for (int j = 0; j < 4; ++j)
                wq[j] = *(const ulonglong2*)&wb[j * 32 * WSROW + 4 * s];
#pragma unroll
            for (int i = 0; i < 8; ++i) {
                const ulonglong2 xv = *(const ulonglong2*)&xb[i * KC + 4 * s];
#pragma unroll
                for (int j = 0; j < 4; ++j) {
                    acc[i][j] = fma2(xv.x, wq[j].x, acc[i][j]);
                    acc[i][j] = fma2(xv.y, wq[j].y, acc[i][j]);
                }
            }
        }
        if (pf) {
            if (v0.x != 0.f || v0.y != 0.f || v0.z != 0.f || v0.w != 0.f) nzs[sfr] = 1;
            if (v1.x != 0.f || v1.y != 0.f || v1.z != 0.f || v1.w != 0.f) nzs[sfr + 32] = 1;
            *(float4*)&xs[nxt * XS_FLOATS + xd0] = v0;
            *(float4*)&xs[nxt * XS_FLOATS + xd1] = v1;
            asm volatile("cp.async.wait_group 0;" ::: "memory");
        }
        __syncthreads();
    }

    // ---- epilogue: relu(+b1)*W2, lane-reduce over u, write scores ----
    // b2 omitted: rank-invariant shift.
    float b1v[4], w2v[4];
#pragma unroll
    for (int j = 0; j < 4; ++j) {
        b1v[j] = b1[l + 32 * j];
        w2v[j] = W2[l + 32 * j];
    }
#pragma unroll
    for (int i = 0; i < 8; ++i) {
        float s_ = 0.f;
#pragma unroll
        for (int j = 0; j < 4; ++j) {
            const float2 p = unpack2(acc[i][j]);
            s_ += fmaxf(p.x + p.y + b1v[j], 0.f) * w2v[j];
        }
#pragma unroll
        for (int off = 16; off > 0; off >>= 1)
            s_ += __shfl_xor_sync(0xffffffffu, s_, off);
        if (l == 0) {
            const int fr = fb + w * 8 + i;
            g_scores[fr] = nzs[w * 8 + i] ? s_ : NEG_BIG;
        }
    }
}

// ---------------- Kernel 2: per-row top-k (iterative argmax, index tiebreak) -
__global__ void topk_kernel(const int* __restrict__ kp) {
    __shared__ float sv[TT];
    __shared__ float bw[8];
    __shared__ int   bi[8];
    const int b = blockIdx.x;
    const int t = threadIdx.x;
    const float* row = g_scores + b * TT;
    int* selrow = g_sel + b * TT;

    for (int i = t; i < TT; i += 256) { sv[i] = row[i]; selrow[i] = 0; }
    __syncthreads();

    int k = kp[0];
    if (k <= 0 || k > TT) k = 64;

    for (int it = 0; it < k; ++it) {
        float best = -FLT_MAX;
        int bidx = TT;
        for (int i = t; i < TT; i += 256) {
            const float v = sv[i];
            if (v > best || (v == best && i < bidx)) { best = v; bidx = i; }
        }
#pragma unroll
        for (int off = 16; off > 0; off >>= 1) {
            const float ov = __shfl_xor_sync(0xffffffffu, best, off);
            const int   oi = __shfl_xor_sync(0xffffffffu, bidx, off);
            if (ov > best || (ov == best && oi < bidx)) { best = ov; bidx = oi; }
        }
        if ((t & 31) == 0) { bw[t >> 5] = best; bi[t >> 5] = bidx; }
        __syncthreads();
        if (t == 0) {
            float b0 = bw[0]; int i0 = bi[0];
#pragma unroll
            for (int j = 1; j < 8; ++j)
                if (bw[j] > b0 || (bw[j] == b0 && bi[j] < i0)) { b0 = bw[j]; i0 = bi[j]; }
            sv[i0] = -FLT_MAX;
            selrow[i0] = 1;
        }
        __syncthreads();
    }
}

// ---------------- Kernel 3: out = sel ? x : 0 (grid-stride float4) ---------
// 256-thread blocks, 4 float4 per thread. Store always; load x only when
// selected (warp-uniform predicate within a frame).
__global__ __launch_bounds__(256)
void scatter_kernel(const float* __restrict__ x, float* __restrict__ out) {
    const float4* x4 = (const float4*)x;
    float4* o4 = (float4*)out;
    const int base = blockIdx.x * 1024 + threadIdx.x;
#pragma unroll
    for (int r = 0; r < 4; ++r) {
        const int i = base + 256 * r;        // float4 index, < 8388608
        const int frame = i >> 7;            // 128 float4 per frame
        float4 v = make_float4(0.f, 0.f, 0.f, 0.f);
        if (g_sel[frame]) v = x4[i];
        o4[i] = v;
    }
}

extern "C" void kernel_launch(void* const* d_in, const int* in_sizes, int n_in,
                              void* d_out, int out_size) {
    const float* x  = (const float*)d_in[0];
    const float* W1 = (const float*)d_in[1];
    const float* b1 = (const float*)d_in[2];
    const float* W2 = (const float*)d_in[3];
    // d_in[4] = b2: rank-invariant, unused.
    const int*   kp = (const int*)d_in[5];
    float* out = (float*)d_out;

    static bool attr_set = false;
    if (!attr_set) {
        cudaFuncSetAttribute(scores_kernel,
                             cudaFuncAttributeMaxDynamicSharedMemorySize,
                             SMEM_BYTES);
        attr_set = true;
    }

    transpose_W1<<<dim3(16, 4), dim3(32, 8)>>>(W1);
    scores_kernel<<<BT / FRB, 256, SMEM_BYTES>>>(x, b1, W2);
    topk_kernel<<<BB, 256>>>(kp);
    scatter_kernel<<<BT * FF / 4 / 1024, 256>>>(x, out);
}

// round 8
// speedup vs baseline: 1.9870x; 1.6873x over previous
#include <cuda_runtime.h>
#include <cuda_bf16.h>
#include <stdint.h>
#include <float.h>

// Problem shape (RLFrameSelector): x[B,T,F], W1[F,U], b1[U], W2[U,1], b2[1], k
#define BB 32
#define TT 2048
#define FF 512
#define UU 128
#define BT (BB * TT)      // 65536 frames
#define NEG_BIG (-1.0e9f)

// ---------------- device scratch (no allocation allowed) --------------------
__device__ float         g_scores[BT];          // approx (bf16-MMA) scores
__device__ int           g_sel[BT];
__device__ float         g_W1T[UU * FF];        // W1^T fp32 [u][f]
__device__ __nv_bfloat16 g_W1Tb[UU * FF];       // W1^T bf16 [u][f]
__device__ int           g_cand[BB * 256];      // global frame indices
__device__ float         g_cand_score[BB * 256];
__device__ int           g_cand_n[BB];

// ======================= helpers ============================================
__device__ __forceinline__ uint32_t smem_u32(const void* p) {
    uint32_t a;
    asm("{ .reg .u64 t; cvta.to.shared.u64 t, %1; cvt.u32.u64 %0, t; }"
        : "=r"(a) : "l"(p));
    return a;
}
__device__ __forceinline__ uint32_t cvt_bf16x2(float hi, float lo) {
    uint32_t r;
    asm("cvt.rn.bf16x2.f32 %0, %1, %2;" : "=r"(r) : "f"(hi), "f"(lo));
    return r;
}
__device__ __forceinline__ unsigned long long fma2(unsigned long long a,
                                                   unsigned long long b,
                                                   unsigned long long c) {
    unsigned long long d;
    asm("fma.rn.f32x2 %0, %1, %2, %3;" : "=l"(d) : "l"(a), "l"(b), "l"(c));
    return d;
}
__device__ __forceinline__ float2 unpack2(unsigned long long v) {
    float2 r;
    asm("mov.b64 {%0, %1}, %2;" : "=f"(r.x), "=f"(r.y) : "l"(v));
    return r;
}
__device__ __forceinline__ void cpasync16(uint32_t dst, const void* src) {
    asm volatile("cp.async.cg.shared.global [%0], [%1], 16;" :: "r"(dst), "l"(src));
}
__device__ __forceinline__ void ldm_x4(uint32_t addr, uint32_t* r) {
    asm volatile("ldmatrix.sync.aligned.m8n8.x4.shared.b16 {%0,%1,%2,%3}, [%4];"
                 : "=r"(r[0]), "=r"(r[1]), "=r"(r[2]), "=r"(r[3]) : "r"(addr));
}
__device__ __forceinline__ void mma16816(float* d, const uint32_t* a,
                                         uint32_t b0, uint32_t b1) {
    asm volatile(
        "mma.sync.aligned.m16n8k16.row.col.f32.bf16.bf16.f32 "
        "{%0,%1,%2,%3}, {%4,%5,%6,%7}, {%8,%9}, {%0,%1,%2,%3};"
        : "+f"(d[0]), "+f"(d[1]), "+f"(d[2]), "+f"(d[3])
        : "r"(a[0]), "r"(a[1]), "r"(a[2]), "r"(a[3]), "r"(b0), "r"(b1));
}

// ---------------- Kernel 0: W1[f][u] -> W1T fp32 + bf16 ---------------------
__global__ void prep_W1(const float* __restrict__ W1) {
    __shared__ float tile[32][33];
    const int bx = blockIdx.x, by = blockIdx.y;
    const int tx = threadIdx.x, ty = threadIdx.y;
#pragma unroll
    for (int i = 0; i < 32; i += 8)
        tile[ty + i][tx] = W1[(bx * 32 + ty + i) * UU + by * 32 + tx];
    __syncthreads();
#pragma unroll
    for (int i = 0; i < 32; i += 8) {
        const int u = by * 32 + ty + i;
        const int f = bx * 32 + tx;
        const float v = tile[tx][ty + i];
        g_W1T[u * FF + f] = v;
        g_W1Tb[u * FF + f] = __float2bfloat16(v);
    }
}

// ---------------- Kernel 1: approx scores via warp-level bf16 MMA -----------
// Per CTA: 128 frames. 8 warps: warp = (frame group wg of 32 fr) x (u-half uh
// of 64 u). K staged in 16 chunks of 32 feats, double buffered.
// smem rows are 64B (32 bf16); swizzle: 16B group g stored at g^((row>>1)&3)
// -> STS.128 staging and all ldmatrix.x4 phases conflict-free.
#define MCH 32                       // features per chunk
#define XTB 8192                     // one x tile: 128 fr x 64 B
#define WTB 8192                     // one W tile: 128 u x 64 B

__global__ __launch_bounds__(256, 2)
void mma_scores(const float* __restrict__ x,
                const float* __restrict__ b1,
                const float* __restrict__ W2) {
    __shared__ char xa[2 * XTB];
    __shared__ char wb[2 * WTB];
    __shared__ float b1s[UU], w2s[UU];
    __shared__ float ps[128][2];
    __shared__ int nzs[128];

    const int t = threadIdx.x;
    const int l = t & 31;
    const int w = t >> 5;
    const int wg = w >> 1;           // frame group (0..3) -> frames wg*32..+32
    const int uh = w & 1;            // u half (0..1)     -> u uh*64..+64
    const int fb = blockIdx.x * 128;

    if (t < UU) { b1s[t] = b1[t]; w2s[t] = W2[t]; }
    if (t < 128) nzs[t] = 0;
    __syncthreads();

    const uint32_t xab = smem_u32(xa);
    const uint32_t wbb = smem_u32(wb);

    // staging mapping: thread t handles row fr=t>>1, half h=t&1 (16 feats)
    const int sfr = t >> 1;
    const int sh = t & 1;
    const float* xsrc = x + (size_t)(fb + sfr) * FF + sh * 16;
    const int sg0 = sh * 2, sg1 = sh * 2 + 1;
    const uint32_t xswz = (uint32_t)(sfr >> 1) & 3;
    const uint32_t xd0 = sfr * 64 + (((sg0 ^ xswz) & 3) << 4);
    const uint32_t xd1 = sfr * 64 + (((sg1 ^ xswz) & 3) << 4);
    const char* wsrc = (const char*)g_W1Tb + (size_t)(sfr * FF) * 2;
    const uint32_t wd0 = sfr * 64 + (((sg0 ^ xswz) & 3) << 4);
    const uint32_t wd1 = sfr * 64 + (((sg1 ^ xswz) & 3) << 4);

    auto stage = [&](int c, int buf) {
        const float4* s4 = (const float4*)(xsrc + c * MCH);
        const float4 v0 = s4[0], v1 = s4[1], v2 = s4[2], v3 = s4[3];
        if (v0.x != 0.f || v0.y != 0.f || v0.z != 0.f || v0.w != 0.f ||
            v1.x != 0.f || v1.y != 0.f || v1.z != 0.f || v1.w != 0.f ||
            v2.x != 0.f || v2.y != 0.f || v2.z != 0.f || v2.w != 0.f ||
            v3.x != 0.f || v3.y != 0.f || v3.z != 0.f || v3.w != 0.f)
            nzs[sfr] = 1;
        uint4 p0, p1;
        p0.x = cvt_bf16x2(v0.y, v0.x);
        p0.y = cvt_bf16x2(v0.w, v0.z);
        p0.z = cvt_bf16x2(v1.y, v1.x);
        p0.w = cvt_bf16x2(v1.w, v1.z);
        p1.x = cvt_bf16x2(v2.y, v2.x);
        p1.y = cvt_bf16x2(v2.w, v2.z);
        p1.z = cvt_bf16x2(v3.y, v3.x);
        p1.w = cvt_bf16x2(v3.w, v3.z);
        *(uint4*)(xa + buf * XTB + xd0) = p0;
        *(uint4*)(xa + buf * XTB + xd1) = p1;
        cpasync16(wbb + buf * WTB + wd0, wsrc + (c * MCH + sg0 * 8) * 2);
        cpasync16(wbb + buf * WTB + wd1, wsrc + (c * MCH + sg1 * 8) * 2);
        asm volatile("cp.async.commit_group;");
    };

    // ldmatrix lane offsets (byte offsets within a tile)
    const int mat = l >> 3, r = l & 7;
    uint32_t aoff[2][2], boff[4][2];
#pragma unroll
    for (int mt = 0; mt < 2; ++mt)
#pragma unroll
        for (int ks = 0; ks < 2; ++ks) {
            const int fr = wg * 32 + mt * 16 + ((mat & 1) << 3) + r;
            const int g = ks * 2 + (mat >> 1);
            aoff[mt][ks] = fr * 64 + (((g ^ ((fr >> 1) & 3)) & 3) << 4);
        }
#pragma unroll
    for (int ng = 0; ng < 4; ++ng)
#pragma unroll
        for (int ks = 0; ks < 2; ++ks) {
            const int u = uh * 64 + ng * 16 + ((mat >> 1) << 3) + r;
            const int g = ks * 2 + (mat & 1);
            boff[ng][ks] = u * 64 + (((g ^ ((u >> 1) & 3)) & 3) << 4);
        }

    float acc[2][8][4];
#pragma unroll
    for (int mt = 0; mt < 2; ++mt)
#pragma unroll
        for (int nt = 0; nt < 8; ++nt)
#pragma unroll
            for (int j = 0; j < 4; ++j) acc[mt][nt][j] = 0.f;

    stage(0, 0);
    asm volatile("cp.async.wait_group 0;" ::: "memory");
    __syncthreads();

    for (int c = 0; c < FF / MCH; ++c) {
        const int cur = c & 1;
        const bool pf = (c + 1 < FF / MCH);
        if (pf) stage(c + 1, cur ^ 1);

        const uint32_t xac = xab + cur * XTB;
        const uint32_t wbc = wbb + cur * WTB;
        uint32_t afr[2][2][4];
#pragma unroll
        for (int mt = 0; mt < 2; ++mt)
#pragma unroll
            for (int ks = 0; ks < 2; ++ks)
                ldm_x4(xac + aoff[mt][ks], afr[mt][ks]);
#pragma unroll
        for (int ng = 0; ng < 4; ++ng) {
            uint32_t b0[4], b1r[4];
            ldm_x4(wbc + boff[ng][0], b0);    // k 0-15 : n-octets 2ng, 2ng+1
            ldm_x4(wbc + boff[ng][1], b1r);   // k 16-31
#pragma unroll
            for (int mt = 0; mt < 2; ++mt) {
                mma16816(acc[mt][2 * ng],     afr[mt][0], b0[0], b0[1]);
                mma16816(acc[mt][2 * ng],     afr[mt][1], b1r[0], b1r[1]);
                mma16816(acc[mt][2 * ng + 1], afr[mt][0], b0[2], b0[3]);
                mma16816(acc[mt][2 * ng + 1], afr[mt][1], b1r[2], b1r[3]);
            }
        }
        if (pf) asm volatile("cp.async.wait_group 0;" ::: "memory");
        __syncthreads();
    }

    // ---- epilogue: relu(h + b1) * W2, reduce u within warp-half ----
    float p[4] = {0.f, 0.f, 0.f, 0.f};   // [mt*2 + rowhalf]
#pragma unroll
    for (int mt = 0; mt < 2; ++mt)
#pragma unroll
        for (int nt = 0; nt < 8; ++nt) {
            const int u0 = uh * 64 + nt * 8 + 2 * (l & 3);
            const int u1 = u0 + 1;
            p[mt * 2 + 0] += fmaxf(acc[mt][nt][0] + b1s[u0], 0.f) * w2s[u0] +
                             fmaxf(acc[mt][nt][1] + b1s[u1], 0.f) * w2s[u1];
            p[mt * 2 + 1] += fmaxf(acc[mt][nt][2] + b1s[u0], 0.f) * w2s[u0] +
                             fmaxf(acc[mt][nt][3] + b1s[u1], 0.f) * w2s[u1];
        }
#pragma unroll
    for (int i = 0; i < 4; ++i) {
        p[i] += __shfl_xor_sync(0xffffffffu, p[i], 1);
        p[i] += __shfl_xor_sync(0xffffffffu, p[i], 2);
    }
    if ((l & 3) == 0) {
#pragma unroll
        for (int mt = 0; mt < 2; ++mt)
#pragma unroll
            for (int rh = 0; rh < 2; ++rh)
                ps[wg * 32 + mt * 16 + rh * 8 + (l >> 2)][uh] = p[mt * 2 + rh];
    }
    __syncthreads();
    if (t < 128) {
        const float s = ps[t][0] + ps[t][1];
        g_scores[fb + t] = nzs[t] ? s : NEG_BIG;
        g_sel[fb + t] = 0;
    }
}

// ---------------- Kernel 2: per-row candidate band via radix histogram ------
__global__ __launch_bounds__(256) void select_kernel(const int* __restrict__ kp) {
    __shared__ unsigned su[TT];
    __shared__ int hist[4096];
    __shared__ int wsuf[8];
    __shared__ int s_bin, s_cnt;
    const int row = blockIdx.x, t = threadIdx.x;
    const int lane = t & 31, wrp = t >> 5;
    int k = kp[0]; if (k < 1 || k > TT) k = 64;
    int R = k + 16; if (R > 256) R = 256;

    for (int i = t; i < 4096; i += 256) hist[i] = 0;
    if (t == 0) s_cnt = 0;
    __syncthreads();
#pragma unroll
    for (int j = 0; j < 8; ++j) {
        const int i = t + 256 * j;
        const unsigned b = __float_as_uint(g_scores[row * TT + i]);
        const unsigned u = (b & 0x80000000u) ? ~b : (b | 0x80000000u);
        su[i] = u;
        atomicAdd(&hist[u >> 20], 1);
    }
    __syncthreads();
    int tot = 0;
#pragma unroll
    for (int j = 0; j < 16; ++j) tot += hist[t * 16 + j];
    int s = tot;
#pragma unroll
    for (int off = 1; off < 32; off <<= 1) {
        const int o = __shfl_down_sync(0xffffffffu, s, off);
        if (lane + off < 32) s += o;
    }
    if (lane == 0) wsuf[wrp] = s;
    __syncthreads();
    if (t == 0) {
        int run = 0;
        for (int w2 = 7; w2 >= 0; --w2) { const int tv = wsuf[w2]; wsuf[w2] = run; run += tv; }
    }
    __syncthreads();
    const int above = wsuf[wrp] + (s - tot);
    if (above < R && above + tot >= R) {
        int run = above;
        for (int j = 15; j >= 0; --j) {
            run += hist[t * 16 + j];
            if (run >= R) { s_bin = t * 16 + j; break; }
        }
    }
    __syncthreads();
    const unsigned thr = ((unsigned)s_bin) << 20;
#pragma unroll
    for (int j = 0; j < 8; ++j) {
        const int i = t + 256 * j;
        if (su[i] >= thr) {
            const int p = atomicAdd(&s_cnt, 1);
            if (p < 256) g_cand[row * 256 + p] = row * TT + i;
        }
    }
    __syncthreads();
    if (t == 0) g_cand_n[row] = s_cnt < 256 ? s_cnt : 256;
}

// ---------------- Kernel 3: exact fp32 rescore of candidates (FFMA2) --------
#define KC 32
#define NCHUNK (FF / KC)
#define WSROW 36
#define XS_FLOATS (64 * KC)
#define WS_FLOATS (UU * WSROW)
#define RS_SMEM ((2 * XS_FLOATS + 2 * WS_FLOATS) * 4 + 64 * 4)  // 53504 B

__global__ __launch_bounds__(256, 2)
void rescore_kernel(const float* __restrict__ x,
                    const float* __restrict__ b1,
                    const float* __restrict__ W2) {
    extern __shared__ float sm[];
    float* xs = sm;
    float* ws = sm + 2 * XS_FLOATS;
    int* cidx = (int*)(sm + 2 * XS_FLOATS + 2 * WS_FLOATS);

    const int t = threadIdx.x;
    const int w = t >> 5;
    const int l = t & 31;
    const int row = blockIdx.x >> 2;
    const int sbase = (blockIdx.x & 3) * 64;
    const int n = g_cand_n[row];

    if (t < 64) {
        const int slot = sbase + t;
        cidx[t] = (slot < n) ? g_cand[row * 256 + slot] : g_cand[row * 256];
    }
    __syncthreads();

    const int sfr = t >> 3;
    const int sj  = (t & 7) * 4;
    const float* xsrc0 = x + (size_t)cidx[sfr] * FF + sj;
    const float* xsrc1 = x + (size_t)cidx[sfr + 32] * FF + sj;
    const int xd0 = sfr * KC + sj;
    const int xd1 = (sfr + 32) * KC + sj;

    {
#pragma unroll
        for (int k2 = 0; k2 < 4; ++k2) {
            const int idx = t + 256 * k2;
            const int u = idx >> 3, jj = (idx & 7) * 4;
            cpasync16(smem_u32(&ws[u * WSROW + jj]), &g_W1T[u * FF + jj]);
        }
        asm volatile("cp.async.commit_group;");
        *(float4*)&xs[xd0] = *(const float4*)xsrc0;
        *(float4*)&xs[xd1] = *(const float4*)xsrc1;
        asm volatile("cp.async.wait_group 0;" ::: "memory");
    }
    __syncthreads();

    unsigned long long acc[8][4];
#pragma unroll
    for (int i = 0; i < 8; ++i)
#pragma unroll
        for (int j = 0; j < 4; ++j) acc[i][j] = 0ull;

    const int xoff = (w * 8) * KC;
    const int woff = l * WSROW;

    for (int c = 0; c < NCHUNK; ++c) {
        const int cur = c & 1, nxt = cur ^ 1;
        const bool pf = (c + 1 < NCHUNK);
        float4 v0, v1;
        if (pf) {
#pragma unroll
            for (int k2 = 0; k2 < 4; ++k2) {
                const int idx = t + 256 * k2;
                const int u = idx >> 3, jj = (idx & 7) * 4;
                cpasync16(smem_u32(&ws[nxt * WS_FLOATS + u * WSROW + jj]),
                          &g_W1T[u * FF + (c + 1) * KC + jj]);
            }
            asm volatile("cp.async.commit_group;");
            v0 = *(const float4*)(xsrc0 + (c + 1) * KC);
            v1 = *(const float4*)(xsrc1 + (c + 1) * KC);
        }
        const float* xb = &xs[cur * XS_FLOATS + xoff];
        const float* wb2 = &ws[cur * WS_FLOATS + woff];
#pragma unroll
        for (int s2 = 0; s2 < KC / 4; ++s2) {
            ulonglong2 wq[4];
#pragma unroll
            for (int j = 0; j < 4; ++j)
                wq[j] = *(const ulonglong2*)&wb2[j * 32 * WSROW + 4 * s2];
#pragma unroll
            for (int i = 0; i < 8; ++i) {
                const ulonglong2 xv = *(const ulonglong2*)&xb[i * KC + 4 * s2];
#pragma unroll
                for (int j = 0; j < 4; ++j) {
                    acc[i][j] = fma2(xv.x, wq[j].x, acc[i][j]);
                    acc[i][j] = fma2(xv.y, wq[j].y, acc[i][j]);
                }
            }
        }
        if (pf) {
            *(float4*)&xs[nxt * XS_FLOATS + xd0] = v0;
            *(float4*)&xs[nxt * XS_FLOATS + xd1] = v1;
            asm volatile("cp.async.wait_group 0;" ::: "memory");
        }
        __syncthreads();
    }

    float b1v[4], w2v[4];
#pragma unroll
    for (int j = 0; j < 4; ++j) {
        b1v[j] = b1[l + 32 * j];
        w2v[j] = W2[l + 32 * j];
    }
#pragma unroll
    for (int i = 0; i < 8; ++i) {
        float s_ = 0.f;
#pragma unroll
        for (int j = 0; j < 4; ++j) {
            const float2 p = unpack2(acc[i][j]);
            s_ += fmaxf(p.x + p.y + b1v[j], 0.f) * w2v[j];
        }
#pragma unroll
        for (int off = 16; off > 0; off >>= 1)
            s_ += __shfl_xor_sync(0xffffffffu, s_, off);
        if (l == 0)
            g_cand_score[row * 256 + sbase + w * 8 + i] = s_;
    }
}

// ---------------- Kernel 4: exact top-k among candidates --------------------
__global__ __launch_bounds__(32) void final_kernel(const int* __restrict__ kp) {
    const int row = blockIdx.x, l = threadIdx.x;
    const int n = g_cand_n[row];
    int k = kp[0]; if (k < 1 || k > TT) k = 64;
    if (k > n) k = n;

    float sc[8]; int fr[8];
#pragma unroll
    for (int j = 0; j < 8; ++j) {
        const int slot = l + 32 * j;
        if (slot < n) {
            sc[j] = g_cand_score[row * 256 + slot];
            fr[j] = g_cand[row * 256 + slot];
        } else { sc[j] = -FLT_MAX; fr[j] = 0x7fffffff; }
    }
    for (int it = 0; it < k; ++it) {
        float bs = -FLT_MAX; int bf = 0x7fffffff; int bj = -1;
#pragma unroll
        for (int j = 0; j < 8; ++j)
            if (sc[j] > bs || (sc[j] == bs && fr[j] < bf)) { bs = sc[j]; bf = fr[j]; bj = j; }
#pragma unroll
        for (int off = 16; off > 0; off >>= 1) {
            const float os = __shfl_xor_sync(0xffffffffu, bs, off);
            const int   of = __shfl_xor_sync(0xffffffffu, bf, off);
            if (os > bs || (os == bs && of < bf)) { bs = os; bf = of; bj = -1; }
        }
        if (bj >= 0 && fr[bj] == bf) { g_sel[bf] = 1; sc[bj] = -FLT_MAX; }
        __syncwarp();
    }
}

// ---------------- Kernel 5: out = sel ? x : 0 -------------------------------
__global__ __launch_bounds__(256)
void scatter_kernel(const float* __restrict__ x, float* __restrict__ out) {
    const float4* x4 = (const float4*)x;
    float4* o4 = (float4*)out;
    const int base = blockIdx.x * 1024 + threadIdx.x;
#pragma unroll
    for (int r = 0; r < 4; ++r) {
        const int i = base + 256 * r;
        const int frame = i >> 7;
        float4 v = make_float4(0.f, 0.f, 0.f, 0.f);
        if (g_sel[frame]) v = x4[i];
        o4[i] = v;
    }
}

extern "C" void kernel_launch(void* const* d_in, const int* in_sizes, int n_in,
                              void* d_out, int out_size) {
    const float* x  = (const float*)d_in[0];
    const float* W1 = (const float*)d_in[1];
    const float* b1 = (const float*)d_in[2];
    const float* W2 = (const float*)d_in[3];
    // d_in[4] = b2: rank-invariant, unused.
    const int*   kp = (const int*)d_in[5];
    float* out = (float*)d_out;

    static bool attr_set = false;
    if (!attr_set) {
        cudaFuncSetAttribute(rescore_kernel,
                             cudaFuncAttributeMaxDynamicSharedMemorySize, RS_SMEM);
        attr_set = true;
    }

    prep_W1<<<dim3(16, 4), dim3(32, 8)>>>(W1);
    mma_scores<<<BT / 128, 256>>>(x, b1, W2);
    select_kernel<<<BB, 256>>>(kp);
    rescore_kernel<<<BB * 4, 256, RS_SMEM>>>(x, b1, W2);
    final_kernel<<<BB, 32>>>(kp);
    scatter_kernel<<<BT * FF / 4 / 1024, 256>>>(x, out);
}